// round 5
// baseline (speedup 1.0000x reference)
#include <cuda_runtime.h>
#include <cuda_fp16.h>
#include <stdint.h>

#define K_DIM 4096
#define N_DIM 14336
#define BATCH 8
#define TK (K_DIM/16)      // 256 k-tiles
#define TN (N_DIM/16)      // 896 n-tiles
#define KSPLIT 4
#define NSTRIPS (TN/2)     // 448 strips of 32 columns

// Promoted dtypes (confirmed): x/suh/svh/bias/out = float32, trellis = int32 (one u16/word).

// Scratch (device globals; no allocation allowed)
__device__ __align__(16) __half g_xh[K_DIM * BATCH];           // [k][8 halves], 16B per k-row
__device__ __align__(16) float g_yp[KSPLIT * BATCH * N_DIM];   // partials [ks][b][n]

// ---------------------------------------------------------------------------
// Warp-local 128-point Hadamard butterfly: lane l holds elements 4l..4l+3.
// Stages h=1,2 in registers; h=4..64 via shfl.bfly. No barriers.
// ---------------------------------------------------------------------------
__device__ __forceinline__ void had128_warp(float v[4], int lane) {
    // h = 1 (within-register, partner i^1)
    {
        float t0 = v[0] + v[1], t1 = v[0] - v[1];
        float t2 = v[2] + v[3], t3 = v[2] - v[3];
        v[0] = t0; v[1] = t1; v[2] = t2; v[3] = t3;
    }
    // h = 2 (within-register, partner i^2)
    {
        float t0 = v[0] + v[2], t2 = v[0] - v[2];
        float t1 = v[1] + v[3], t3 = v[1] - v[3];
        v[0] = t0; v[1] = t1; v[2] = t2; v[3] = t3;
    }
    // h = 4..64 -> lane butterflies with mask m = h/4 = 1..16
#pragma unroll
    for (int m = 1; m < 32; m <<= 1) {
        bool up = (lane & m);
#pragma unroll
        for (int i = 0; i < 4; i++) {
            float o = __shfl_xor_sync(0xFFFFFFFFu, v[i], m);
            v[i] = up ? (o - v[i]) : (v[i] + o);
        }
    }
}

// ---------------------------------------------------------------------------
// Kernel 1: xh = Had128(x * suh) -> fp16, k-major [k][8]
// grid 32 blocks x 256 threads; warp w handles batch-row w, k-block = blockIdx
// ---------------------------------------------------------------------------
__global__ void __launch_bounds__(256) k_had_in(const float* __restrict__ x,
                                                const float* __restrict__ suh) {
    int lane = threadIdx.x & 31;
    int row = threadIdx.x >> 5;        // 0..7
    int kb = blockIdx.x * 128;
    float4 xv = *(const float4*)(x + row * K_DIM + kb + 4 * lane);
    float4 sv = *(const float4*)(suh + kb + 4 * lane);
    float v[4] = {xv.x * sv.x, xv.y * sv.y, xv.z * sv.z, xv.w * sv.w};
    had128_warp(v, lane);
#pragma unroll
    for (int i = 0; i < 4; i++)
        g_xh[(kb + 4 * lane + i) * BATCH + row] = __float2half(v[i] * 0.08838834764831845f);
}

// ---------------------------------------------------------------------------
// Kernel 2: main dequant + GEMM. grid = NSTRIPS*KSPLIT, 128 threads (4 warps).
// Each warp: 32 columns (2 adjacent trellis tiles), 16 k-tiles.
// ---------------------------------------------------------------------------
__global__ void __launch_bounds__(128) k_main(const int* __restrict__ trellis) {
    int bid = blockIdx.x;
    int strip = bid >> 2;            // 0..447
    int ks = bid & 3;                // k-slice
    int tid = threadIdx.x;
    int warp = tid >> 5, lane = tid & 31;
    int tn0 = strip * 2;

    int tsel = lane >> 4;            // which of the two tiles
    int c = lane & 15;               // column within tile
    int c3 = 3 * c;
    int c3h = c3 >> 4;               // word offset within row (0..2)
    int sh = 16 - (c3 & 15);         // shift (1..16)
    unsigned int cbase = (unsigned)(tsel * 48 + c3h);

    __shared__ unsigned int rawS[4][48];   // 96 u16 (2 tiles) per warp
    __shared__ unsigned int combS[4][96];  // precombined 32-bit windows
    __shared__ uint4 xS[4][16];            // x tile: 16 k-rows x 8 fp16

    float fa[8] = {0.f, 0.f, 0.f, 0.f, 0.f, 0.f, 0.f, 0.f};

    int tkBase = ks * (TK / KSPLIT) + warp * (TK / KSPLIT / 4);   // ks*64 + warp*16
#pragma unroll 1
    for (int tki = 0; tki < TK / KSPLIT / 4; ++tki) {             // 16 iters
        int tk = tkBase + tki;
        size_t tbase = ((size_t)tk * TN + tn0) * 48;              // in words

        unsigned short* r16 = (unsigned short*)rawS[warp];
        const int* tp32 = trellis + tbase;                        // 96 contiguous int32
#pragma unroll
        for (int j = 0; j < 3; j++) {
            int idx = lane + j * 32;
            r16[idx] = (unsigned short)tp32[idx];
        }
        if (lane < 16) xS[warp][lane] = ((const uint4*)g_xh)[tk * 16 + lane];
        __syncwarp();

#pragma unroll
        for (int j = 0; j < 3; j++) {
            int idx = lane + j * 32;               // 0..95
            int tile = (idx >= 48) ? 1 : 0;
            int w = idx - tile * 48;
            int wn = (w + 1 == 48) ? 0 : (w + 1);  // tail-biting wrap
            combS[warp][idx] = __byte_perm((unsigned int)r16[tile * 48 + wn],
                                           (unsigned int)r16[tile * 48 + w], 0x5410);
        }
        __syncwarp();

        __half2 ah0 = __float2half2_rn(0.f), ah1 = ah0, ah2 = ah0, ah3 = ah0;
#pragma unroll
        for (int r = 0; r < 16; r++) {
            unsigned int comb = combS[warp][cbase + 3 * r];
            unsigned int st = (comb >> sh) & 0xFFFFu;
            unsigned int z = st * 89226354u + 64248484u;
            z &= 0x8FFF8FFFu;
            __half2 zh = *(const __half2*)&z;
            // scalar hadd + dup: ptxas folds into HADD2 / HFMA2 half-lane selectors
            __half ws = __hadd(__low2half(zh), __high2half(zh));
            __half2 w2 = __half2half2(ws);
            uint4 xv = xS[warp][r];                // LDS.128 broadcast
            ah0 = __hfma2(w2, *(const __half2*)&xv.x, ah0);
            ah1 = __hfma2(w2, *(const __half2*)&xv.y, ah1);
            ah2 = __hfma2(w2, *(const __half2*)&xv.z, ah2);
            ah3 = __hfma2(w2, *(const __half2*)&xv.w, ah3);
        }
        // flush fp16 accumulators to fp32 every k-tile (16 adds) for precision
        {
            float2 f;
            f = __half22float2(ah0); fa[0] += f.x; fa[1] += f.y;
            f = __half22float2(ah1); fa[2] += f.x; fa[3] += f.y;
            f = __half22float2(ah2); fa[4] += f.x; fa[5] += f.y;
            f = __half22float2(ah3); fa[6] += f.x; fa[7] += f.y;
        }
        __syncwarp();
    }

    // ---- deterministic block reduction over the 4 warps ----
    __shared__ float redS[4][256];   // [warp][col*8 + b]
#pragma unroll
    for (int b = 0; b < 8; b++) redS[warp][lane * 8 + b] = fa[b];
    __syncthreads();

#pragma unroll
    for (int i = tid; i < 256; i += 128) {
        int col = i & 31, b = i >> 5;
        int idx = col * 8 + b;
        float s = redS[0][idx] + redS[1][idx] + redS[2][idx] + redS[3][idx];
        g_yp[((size_t)ks * BATCH + b) * N_DIM + strip * 32 + col] = s;
    }
}

// ---------------------------------------------------------------------------
// Kernel 3: sum partials, Had128 over N, *svh + bias -> float32 out
// grid 112 blocks x 256 threads; warp w = batch-row w, n-block = blockIdx
// ---------------------------------------------------------------------------
__global__ void __launch_bounds__(256) k_epi(const float* __restrict__ svh,
                                             const float* __restrict__ bias,
                                             float* __restrict__ out) {
    int lane = threadIdx.x & 31;
    int row = threadIdx.x >> 5;        // 0..7
    int nb = blockIdx.x * 128;
    int n0 = nb + 4 * lane;
    float v[4] = {0.f, 0.f, 0.f, 0.f};
#pragma unroll
    for (int ksl = 0; ksl < KSPLIT; ksl++) {
        float4 p = *(const float4*)(g_yp + ((size_t)ksl * BATCH + row) * N_DIM + n0);
        v[0] += p.x; v[1] += p.y; v[2] += p.z; v[3] += p.w;
    }
    had128_warp(v, lane);
    float4 sv = *(const float4*)(svh + n0);
    float4 bv = *(const float4*)(bias + n0);
    float4 o;
    o.x = v[0] * 0.08838834764831845f * sv.x + bv.x;
    o.y = v[1] * 0.08838834764831845f * sv.y + bv.y;
    o.z = v[2] * 0.08838834764831845f * sv.z + bv.z;
    o.w = v[3] * 0.08838834764831845f * sv.w + bv.w;
    *(float4*)(out + row * N_DIM + n0) = o;
}

// ---------------------------------------------------------------------------
extern "C" void kernel_launch(void* const* d_in, const int* in_sizes, int n_in,
                              void* d_out, int out_size) {
    const float* x = (const float*)d_in[0];
    const int* trellis = (const int*)d_in[1];
    const float* suh = (const float*)d_in[2];
    const float* svh = (const float*)d_in[3];
    const float* bias = (const float*)d_in[4];
    float* out = (float*)d_out;

    k_had_in<<<32, 256>>>(x, suh);
    k_main<<<NSTRIPS * KSPLIT, 128>>>(trellis);
    k_epi<<<112, 256>>>(svh, bias, out);
}

// round 6
// speedup vs baseline: 1.4344x; 1.4344x over previous
#include <cuda_runtime.h>
#include <cuda_fp16.h>
#include <stdint.h>

#define K_DIM 4096
#define N_DIM 14336
#define BATCH 8
#define TK (K_DIM/16)      // 256 k-tiles
#define TN (N_DIM/16)      // 896 n-tiles
#define KSPLIT 2
#define NSTRIPS (TN/2)     // 448 strips of 32 columns

// Promoted dtypes (confirmed): x/suh/svh/bias/out = float32, trellis = int32 (one u16/word).

// Scratch (device globals; no allocation allowed)
// g_xB: B-fragments for mma.m16n8k16: per k-tile, per lane: {b0,b1} packed half2s.
__device__ __align__(16) uint2 g_xB[TK * 32];
__device__ __align__(16) float g_yp[KSPLIT * BATCH * N_DIM];   // partials [ks][b][n]

// ---------------------------------------------------------------------------
// Warp-local 128-point Hadamard: lane l holds elements 4l..4l+3. No barriers.
// ---------------------------------------------------------------------------
__device__ __forceinline__ void had128_warp(float v[4], int lane) {
    {
        float t0 = v[0] + v[1], t1 = v[0] - v[1];
        float t2 = v[2] + v[3], t3 = v[2] - v[3];
        v[0] = t0; v[1] = t1; v[2] = t2; v[3] = t3;
    }
    {
        float t0 = v[0] + v[2], t2 = v[0] - v[2];
        float t1 = v[1] + v[3], t3 = v[1] - v[3];
        v[0] = t0; v[1] = t1; v[2] = t2; v[3] = t3;
    }
#pragma unroll
    for (int m = 1; m < 32; m <<= 1) {
        bool up = (lane & m);
#pragma unroll
        for (int i = 0; i < 4; i++) {
            float o = __shfl_xor_sync(0xFFFFFFFFu, v[i], m);
            v[i] = up ? (o - v[i]) : (v[i] + o);
        }
    }
}

// ---------------------------------------------------------------------------
// Kernel 1: xh = Had128(x * suh) -> fp16, packed directly as MMA B-fragments.
// grid 32 blocks x 256 threads. Warp w = batch row w for this 128-k block;
// then a transpose/pack phase emits g_xB for the 8 k-tiles of this block.
// ---------------------------------------------------------------------------
__global__ void __launch_bounds__(256) k_had_in(const float* __restrict__ x,
                                                const float* __restrict__ suh) {
    __shared__ __half sx[8][136];     // padded: bank-conflict-free transpose
    int lane = threadIdx.x & 31;
    int row = threadIdx.x >> 5;        // batch row 0..7
    int kb = blockIdx.x * 128;
    float4 xv = *(const float4*)(x + row * K_DIM + kb + 4 * lane);
    float4 sv = *(const float4*)(suh + kb + 4 * lane);
    float v[4] = {xv.x * sv.x, xv.y * sv.y, xv.z * sv.z, xv.w * sv.w};
    had128_warp(v, lane);
#pragma unroll
    for (int i = 0; i < 4; i++)
        sx[row][4 * lane + i] = __float2half(v[i] * 0.08838834764831845f);
    __syncthreads();

    // pack phase: thread t -> (k-tile tl = t>>5, lane l = t&31)
    int tl = threadIdx.x >> 5;
    int gid = lane >> 2, tig = lane & 3;
    int k0 = tl * 16 + 2 * tig;
    __half h0 = sx[gid][k0],     h1 = sx[gid][k0 + 1];
    __half h2 = sx[gid][k0 + 8], h3 = sx[gid][k0 + 9];
    __half2 b0 = __halves2half2(h0, h1);
    __half2 b1 = __halves2half2(h2, h3);
    uint2 o;
    o.x = *(const unsigned int*)&b0;
    o.y = *(const unsigned int*)&b1;
    g_xB[(blockIdx.x * 8 + tl) * 32 + lane] = o;
}

// ---------------------------------------------------------------------------
// decode_pair: decode weights (rbase, c) and (rbase+1, c) of one tile into a
// packed half2 (A-fragment register). comb holds precombined 32-bit windows.
// ---------------------------------------------------------------------------
__device__ __forceinline__ unsigned int decode_pair(const unsigned int* comb,
                                                    int idx, int sh) {
    unsigned int w0 = comb[idx];
    unsigned int w1 = comb[idx + 3];
    unsigned int s0 = (w0 >> sh) & 0xFFFFu;
    unsigned int s1 = (w1 >> sh) & 0xFFFFu;
    unsigned int z0 = (s0 * 89226354u + 64248484u) & 0x8FFF8FFFu;
    unsigned int z1 = (s1 * 89226354u + 64248484u) & 0x8FFF8FFFu;
    unsigned int lo = __byte_perm(z0, z1, 0x5410);   // (z0.lo16, z1.lo16)
    unsigned int hi = __byte_perm(z0, z1, 0x7632);   // (z0.hi16, z1.hi16)
    __half2 r = __hadd2(*(const __half2*)&lo, *(const __half2*)&hi);
    return *(const unsigned int*)&r;                 // {w(rbase,c), w(rbase+1,c)}
}

// ---------------------------------------------------------------------------
// Kernel 2: main dequant + tensor-core GEMM.
// grid = NSTRIPS*KSPLIT = 896 blocks, 128 threads (4 warps).
// Each warp: 32 columns (2 trellis tiles = 2 MMA m16 groups), 32 k-tiles.
// ---------------------------------------------------------------------------
__global__ void __launch_bounds__(128) k_main(const int* __restrict__ trellis) {
    int bid = blockIdx.x;
    int strip = bid >> 1;            // 0..447
    int ks = bid & 1;                // k-slice
    int tid = threadIdx.x;
    int warp = tid >> 5, lane = tid & 31;
    int tn0 = strip * 2;

    int gid = lane >> 2, tig = lane & 3;
    int r0 = 2 * tig;                // A-frag rows r0, r0+1, r0+8, r0+9
    int cA = gid, cB = gid + 8;      // A-frag cols within a 16-col tile
    int c3hA = (3 * cA) >> 4, shA = 16 - ((3 * cA) & 15);
    int c3hB = (3 * cB) >> 4, shB = 16 - ((3 * cB) & 15);

    __shared__ unsigned int rawS[4][48];   // 96 u16 (2 tiles) per warp
    __shared__ unsigned int combS[4][96];  // precombined 32-bit windows

    float d0[4] = {0.f, 0.f, 0.f, 0.f};   // MMA group 0 (cols 0-15)
    float d1[4] = {0.f, 0.f, 0.f, 0.f};   // MMA group 1 (cols 16-31)

    int tkBase = ks * (TK / KSPLIT) + warp * (TK / KSPLIT / 4);   // ks*128 + warp*32
#pragma unroll 1
    for (int tki = 0; tki < TK / KSPLIT / 4; ++tki) {             // 32 iters
        int tk = tkBase + tki;
        size_t tbase = ((size_t)tk * TN + tn0) * 48;              // in words

        // B-fragment for this k-tile (shared by both MMAs)
        uint2 bfr = g_xB[tk * 32 + lane];

        unsigned short* r16 = (unsigned short*)rawS[warp];
        const int* tp32 = trellis + tbase;                        // 96 contiguous int32
#pragma unroll
        for (int j = 0; j < 3; j++) {
            int idx = lane + j * 32;
            r16[idx] = (unsigned short)tp32[idx];
        }
        __syncwarp();

#pragma unroll
        for (int j = 0; j < 3; j++) {
            int idx = lane + j * 32;               // 0..95
            int tile = (idx >= 48) ? 1 : 0;
            int w = idx - tile * 48;
            int wn = (w + 1 == 48) ? 0 : (w + 1);  // tail-biting wrap
            combS[warp][idx] = __byte_perm((unsigned int)r16[tile * 48 + wn],
                                           (unsigned int)r16[tile * 48 + w], 0x5410);
        }
        __syncwarp();

        const unsigned int* comb = combS[warp];
#pragma unroll
        for (int g = 0; g < 2; g++) {
            int base = g * 48;
            unsigned int a0 = decode_pair(comb, base + 3 * r0 + c3hA, shA);
            unsigned int a1 = decode_pair(comb, base + 3 * r0 + c3hB, shB);
            unsigned int a2 = decode_pair(comb, base + 3 * (r0 + 8) + c3hA, shA);
            unsigned int a3 = decode_pair(comb, base + 3 * (r0 + 8) + c3hB, shB);
            float* d = g ? d1 : d0;
            asm volatile(
                "mma.sync.aligned.m16n8k16.row.col.f32.f16.f16.f32 "
                "{%0,%1,%2,%3}, {%4,%5,%6,%7}, {%8,%9}, {%0,%1,%2,%3};"
                : "+f"(d[0]), "+f"(d[1]), "+f"(d[2]), "+f"(d[3])
                : "r"(a0), "r"(a1), "r"(a2), "r"(a3), "r"(bfr.x), "r"(bfr.y));
        }
        __syncwarp();
    }

    // ---- deterministic block reduction over the 4 warps ----
    // C-frag mapping: d[j]: col = g*16 + gid + (j>=2 ? 8 : 0), b = 2*tig + (j&1)
    __shared__ float redS[4][256];   // [warp][col*8 + b]
#pragma unroll
    for (int g = 0; g < 2; g++) {
        const float* d = g ? d1 : d0;
#pragma unroll
        for (int j = 0; j < 4; j++) {
            int col = g * 16 + gid + ((j >> 1) << 3);
            int b = 2 * tig + (j & 1);
            redS[warp][col * 8 + b] = d[j];
        }
    }
    __syncthreads();

#pragma unroll
    for (int i = tid; i < 256; i += 128) {
        int col = i & 31, b = i >> 5;
        int idx = col * 8 + b;
        float s = redS[0][idx] + redS[1][idx] + redS[2][idx] + redS[3][idx];
        g_yp[((size_t)ks * BATCH + b) * N_DIM + strip * 32 + col] = s;
    }
}

// ---------------------------------------------------------------------------
// Kernel 3: sum partials, Had128 over N, *svh + bias -> float32 out
// grid 112 blocks x 256 threads; warp w = batch-row w
// ---------------------------------------------------------------------------
__global__ void __launch_bounds__(256) k_epi(const float* __restrict__ svh,
                                             const float* __restrict__ bias,
                                             float* __restrict__ out) {
    int lane = threadIdx.x & 31;
    int row = threadIdx.x >> 5;        // 0..7
    int n0 = blockIdx.x * 128 + 4 * lane;
    float v[4] = {0.f, 0.f, 0.f, 0.f};
#pragma unroll
    for (int ksl = 0; ksl < KSPLIT; ksl++) {
        float4 p = *(const float4*)(g_yp + ((size_t)ksl * BATCH + row) * N_DIM + n0);
        v[0] += p.x; v[1] += p.y; v[2] += p.z; v[3] += p.w;
    }
    had128_warp(v, lane);
    float4 sv = *(const float4*)(svh + n0);
    float4 bv = *(const float4*)(bias + n0);
    float4 o;
    o.x = v[0] * 0.08838834764831845f * sv.x + bv.x;
    o.y = v[1] * 0.08838834764831845f * sv.y + bv.y;
    o.z = v[2] * 0.08838834764831845f * sv.z + bv.z;
    o.w = v[3] * 0.08838834764831845f * sv.w + bv.w;
    *(float4*)(out + row * N_DIM + n0) = o;
}

// ---------------------------------------------------------------------------
extern "C" void kernel_launch(void* const* d_in, const int* in_sizes, int n_in,
                              void* d_out, int out_size) {
    const float* x = (const float*)d_in[0];
    const int* trellis = (const int*)d_in[1];
    const float* suh = (const float*)d_in[2];
    const float* svh = (const float*)d_in[3];
    const float* bias = (const float*)d_in[4];
    float* out = (float*)d_out;

    k_had_in<<<32, 256>>>(x, suh);
    k_main<<<NSTRIPS * KSPLIT, 128>>>(trellis);
    k_epi<<<112, 256>>>(svh, bias, out);
}

// round 7
// speedup vs baseline: 2.0895x; 1.4568x over previous
#include <cuda_runtime.h>
#include <cuda_fp16.h>
#include <stdint.h>

#define K_DIM 4096
#define N_DIM 14336
#define BATCH 8
#define TK (K_DIM/16)      // 256 k-tiles
#define TN (N_DIM/16)      // 896 n-tiles
#define KSPLIT 4
#define NSTRIPS (TN/2)     // 448 strips of 32 columns

// Promoted dtypes (confirmed): x/suh/svh/bias/out = float32, trellis = int32 (one u16/word).

// Scratch (device globals; no allocation allowed)
// g_xB: B-fragments for mma.m16n8k16: per k-tile, per lane: {b0,b1} packed half2s.
__device__ __align__(16) uint2 g_xB[TK * 32];
__device__ __align__(16) float g_yp[KSPLIT * BATCH * N_DIM];   // partials [ks][b][n]

// ---------------------------------------------------------------------------
// Warp-local 128-point Hadamard: lane l holds elements 4l..4l+3. No barriers.
// ---------------------------------------------------------------------------
__device__ __forceinline__ void had128_warp(float v[4], int lane) {
    {
        float t0 = v[0] + v[1], t1 = v[0] - v[1];
        float t2 = v[2] + v[3], t3 = v[2] - v[3];
        v[0] = t0; v[1] = t1; v[2] = t2; v[3] = t3;
    }
    {
        float t0 = v[0] + v[2], t2 = v[0] - v[2];
        float t1 = v[1] + v[3], t3 = v[1] - v[3];
        v[0] = t0; v[1] = t1; v[2] = t2; v[3] = t3;
    }
#pragma unroll
    for (int m = 1; m < 32; m <<= 1) {
        bool up = (lane & m);
#pragma unroll
        for (int i = 0; i < 4; i++) {
            float o = __shfl_xor_sync(0xFFFFFFFFu, v[i], m);
            v[i] = up ? (o - v[i]) : (v[i] + o);
        }
    }
}

// ---------------------------------------------------------------------------
// Kernel 1: xh = Had128(x * suh) -> fp16, packed directly as MMA B-fragments.
// grid 32 x 256 threads. Warp w = batch row w; pack phase emits g_xB.
// ---------------------------------------------------------------------------
__global__ void __launch_bounds__(256) k_had_in(const float* __restrict__ x,
                                                const float* __restrict__ suh) {
    __shared__ __half sx[8][136];     // padded transpose buffer
    int lane = threadIdx.x & 31;
    int row = threadIdx.x >> 5;        // batch row 0..7
    int kb = blockIdx.x * 128;
    float4 xv = *(const float4*)(x + row * K_DIM + kb + 4 * lane);
    float4 sv = *(const float4*)(suh + kb + 4 * lane);
    float v[4] = {xv.x * sv.x, xv.y * sv.y, xv.z * sv.z, xv.w * sv.w};
    had128_warp(v, lane);
#pragma unroll
    for (int i = 0; i < 4; i++)
        sx[row][4 * lane + i] = __float2half(v[i] * 0.08838834764831845f);
    __syncthreads();

    // pack phase: thread t -> (k-tile tl = t>>5, lane l = t&31)
    int tl = threadIdx.x >> 5;
    int gid = lane >> 2, tig = lane & 3;
    int k0 = tl * 16 + 2 * tig;
    __half2 b0 = __halves2half2(sx[gid][k0], sx[gid][k0 + 1]);
    __half2 b1 = __halves2half2(sx[gid][k0 + 8], sx[gid][k0 + 9]);
    uint2 o;
    o.x = *(const unsigned int*)&b0;
    o.y = *(const unsigned int*)&b1;
    g_xB[(blockIdx.x * 8 + tl) * 32 + lane] = o;
}

// ---------------------------------------------------------------------------
// decode_pair: decode weights (rbase, c) and (rbase+1, c) of one tile into a
// packed half2 (A-fragment register).
// ---------------------------------------------------------------------------
__device__ __forceinline__ unsigned int decode_pair(const unsigned int* comb,
                                                    int idx, int sh) {
    unsigned int w0 = comb[idx];
    unsigned int w1 = comb[idx + 3];
    unsigned int s0 = (w0 >> sh) & 0xFFFFu;
    unsigned int s1 = (w1 >> sh) & 0xFFFFu;
    unsigned int z0 = (s0 * 89226354u + 64248484u) & 0x8FFF8FFFu;
    unsigned int z1 = (s1 * 89226354u + 64248484u) & 0x8FFF8FFFu;
    unsigned int lo = __byte_perm(z0, z1, 0x5410);   // (z0.lo16, z1.lo16)
    unsigned int hi = __byte_perm(z0, z1, 0x7632);   // (z0.hi16, z1.hi16)
    __half2 r = __hadd2(*(const __half2*)&lo, *(const __half2*)&hi);
    return *(const unsigned int*)&r;                 // {w(rbase,c), w(rbase+1,c)}
}

// ---------------------------------------------------------------------------
// Kernel 2: main dequant + tensor-core GEMM, software-pipelined.
// grid = NSTRIPS*KSPLIT = 1792 blocks, 128 threads (4 warps).
// Each warp: 32 columns (2 trellis tiles), 16 k-tiles, prefetch depth 1.
// ---------------------------------------------------------------------------
__global__ void __launch_bounds__(128) k_main(const int* __restrict__ trellis) {
    int bid = blockIdx.x;
    int strip = bid >> 2;            // 0..447
    int ks = bid & 3;                // k-slice
    int tid = threadIdx.x;
    int warp = tid >> 5, lane = tid & 31;
    int tn0 = strip * 2;

    int gid = lane >> 2, tig = lane & 3;
    int r0 = 2 * tig;                // A-frag rows r0, r0+1, r0+8, r0+9
    int cA = gid, cB = gid + 8;      // A-frag cols within a 16-col tile
    int c3hA = (3 * cA) >> 4, shA = 16 - ((3 * cA) & 15);
    int c3hB = (3 * cB) >> 4, shB = 16 - ((3 * cB) & 15);

    __shared__ unsigned int rawS[4][48];   // 96 u16 (2 tiles) per warp
    __shared__ unsigned int combS[4][96];  // precombined 32-bit windows

    float d0[4] = {0.f, 0.f, 0.f, 0.f};   // MMA group 0 (cols 0-15)
    float d1[4] = {0.f, 0.f, 0.f, 0.f};   // MMA group 1 (cols 16-31)

    const int NIT = TK / KSPLIT / 4;                  // 16
    int tkBase = ks * (TK / KSPLIT) + warp * NIT;
    int tkLast = tkBase + NIT - 1;

    // ---- prefetch iteration 0 ----
    int tk = tkBase;
    {
        const int* tp = trellis + (tk * TN + tn0) * 48;
        // nothing else; loads issued below
    }
    const int* tp = trellis + (tk * TN + tn0) * 48;
    int p0 = tp[lane], p1 = tp[lane + 32], p2 = tp[lane + 64];
    uint2 bfr = g_xB[tk * 32 + lane];

#pragma unroll 1
    for (int tki = 0; tki < NIT; ++tki) {
        // ---- stage prefetched trellis words into smem as u16 ----
        unsigned short* r16 = (unsigned short*)rawS[warp];
        r16[lane] = (unsigned short)p0;
        r16[lane + 32] = (unsigned short)p1;
        r16[lane + 64] = (unsigned short)p2;
        __syncwarp();

        // ---- build precombined 32-bit windows ----
#pragma unroll
        for (int j = 0; j < 3; j++) {
            int idx = lane + j * 32;               // 0..95
            int tile = (idx >= 48) ? 1 : 0;
            int w = idx - tile * 48;
            int wn = (w + 1 == 48) ? 0 : (w + 1);  // tail-biting wrap
            combS[warp][idx] = __byte_perm((unsigned int)r16[tile * 48 + wn],
                                           (unsigned int)r16[tile * 48 + w], 0x5410);
        }

        // ---- issue next iteration's global loads (overlap with decode) ----
        int tkn = (tk < tkLast) ? (tk + 1) : tk;
        const int* tpn = trellis + (tkn * TN + tn0) * 48;
        int q0 = tpn[lane], q1 = tpn[lane + 32], q2 = tpn[lane + 64];
        uint2 bfrn = g_xB[tkn * 32 + lane];
        __syncwarp();

        // ---- decode A-fragments + tensor MMA ----
        const unsigned int* comb = combS[warp];
#pragma unroll
        for (int g = 0; g < 2; g++) {
            int base = g * 48;
            unsigned int a0 = decode_pair(comb, base + 3 * r0 + c3hA, shA);
            unsigned int a1 = decode_pair(comb, base + 3 * r0 + c3hB, shB);
            unsigned int a2 = decode_pair(comb, base + 3 * (r0 + 8) + c3hA, shA);
            unsigned int a3 = decode_pair(comb, base + 3 * (r0 + 8) + c3hB, shB);
            float* d = g ? d1 : d0;
            asm volatile(
                "mma.sync.aligned.m16n8k16.row.col.f32.f16.f16.f32 "
                "{%0,%1,%2,%3}, {%4,%5,%6,%7}, {%8,%9}, {%0,%1,%2,%3};"
                : "+f"(d[0]), "+f"(d[1]), "+f"(d[2]), "+f"(d[3])
                : "r"(a0), "r"(a1), "r"(a2), "r"(a3), "r"(bfr.x), "r"(bfr.y));
        }
        __syncwarp();

        p0 = q0; p1 = q1; p2 = q2; bfr = bfrn;
        tk = tkn;
    }

    // ---- deterministic block reduction over the 4 warps ----
    // C-frag mapping: d[j]: col = g*16 + gid + (j>=2 ? 8 : 0), b = 2*tig + (j&1)
    __shared__ float redS[4][256];   // [warp][col*8 + b]
#pragma unroll
    for (int g = 0; g < 2; g++) {
        const float* d = g ? d1 : d0;
#pragma unroll
        for (int j = 0; j < 4; j++) {
            int col = g * 16 + gid + ((j >> 1) << 3);
            int b = 2 * tig + (j & 1);
            redS[warp][col * 8 + b] = d[j];
        }
    }
    __syncthreads();

#pragma unroll
    for (int i = tid; i < 256; i += 128) {
        int col = i & 31, b = i >> 5;
        int idx = col * 8 + b;
        float s = redS[0][idx] + redS[1][idx] + redS[2][idx] + redS[3][idx];
        g_yp[((size_t)ks * BATCH + b) * N_DIM + strip * 32 + col] = s;
    }
}

// ---------------------------------------------------------------------------
// Kernel 3: sum partials, Had128 over N, *svh + bias -> float32 out
// grid 112 x 256 threads; warp w = batch-row w
// ---------------------------------------------------------------------------
__global__ void __launch_bounds__(256) k_epi(const float* __restrict__ svh,
                                             const float* __restrict__ bias,
                                             float* __restrict__ out) {
    int lane = threadIdx.x & 31;
    int row = threadIdx.x >> 5;        // 0..7
    int n0 = blockIdx.x * 128 + 4 * lane;
    float v[4] = {0.f, 0.f, 0.f, 0.f};
#pragma unroll
    for (int ksl = 0; ksl < KSPLIT; ksl++) {
        float4 p = *(const float4*)(g_yp + ((size_t)ksl * BATCH + row) * N_DIM + n0);
        v[0] += p.x; v[1] += p.y; v[2] += p.z; v[3] += p.w;
    }
    had128_warp(v, lane);
    float4 sv = *(const float4*)(svh + n0);
    float4 bv = *(const float4*)(bias + n0);
    float4 o;
    o.x = v[0] * 0.08838834764831845f * sv.x + bv.x;
    o.y = v[1] * 0.08838834764831845f * sv.y + bv.y;
    o.z = v[2] * 0.08838834764831845f * sv.z + bv.z;
    o.w = v[3] * 0.08838834764831845f * sv.w + bv.w;
    *(float4*)(out + row * N_DIM + n0) = o;
}

// ---------------------------------------------------------------------------
extern "C" void kernel_launch(void* const* d_in, const int* in_sizes, int n_in,
                              void* d_out, int out_size) {
    const float* x = (const float*)d_in[0];
    const int* trellis = (const int*)d_in[1];
    const float* suh = (const float*)d_in[2];
    const float* svh = (const float*)d_in[3];
    const float* bias = (const float*)d_in[4];
    float* out = (float*)d_out;

    k_had_in<<<32, 256>>>(x, suh);
    k_main<<<NSTRIPS * KSPLIT, 128>>>(trellis);
    k_epi<<<112, 256>>>(svh, bias, out);
}